// round 2
// baseline (speedup 1.0000x reference)
#include <cuda_runtime.h>

#define G       180
#define NA      64
#define B       27
#define RMAX    13
#define NCELL   (B*B*B)      // 19683
#define SPLIT   2
#define THREADS 256
#define NWARP   (THREADS/32)
#define AH      0.2f
#define ROF     2.5f
#define VCELLF  0.008f

// deterministic two-stage reduction scratch + per-atom arrival counters
__device__ float        g_partial[NA * SPLIT * 128];
__device__ unsigned int g_count[NA];   // zero-init; reset by combiner each run

__device__ __forceinline__ unsigned long long pk2(float lo, float hi) {
    unsigned long long r;
    asm("mov.b64 %0, {%1, %2};" : "=l"(r) : "f"(lo), "f"(hi));
    return r;
}
__device__ __forceinline__ void upk2(float& lo, float& hi, unsigned long long v) {
    asm("mov.b64 {%0, %1}, %2;" : "=f"(lo), "=f"(hi) : "l"(v));
}
__device__ __forceinline__ void fma2(unsigned long long& d,
                                     unsigned long long a, unsigned long long b) {
    asm("fma.rn.f32x2 %0, %1, %2, %0;" : "+l"(d) : "l"(a), "l"(b));
}
__device__ __forceinline__ unsigned long long mul2(unsigned long long a,
                                                   unsigned long long b) {
    unsigned long long r;
    asm("mul.rn.f32x2 %0, %1, %2;" : "=l"(r) : "l"(a), "l"(b));
    return r;
}

__global__ __launch_bounds__(THREADS, 1)
void proj_kernel(const float* __restrict__ rho, const float* __restrict__ pos,
                 const float* __restrict__ W, float* __restrict__ out)
{
    const int blk  = blockIdx.x;
    const int atom = blk / SPLIT;
    const int part = blk % SPLIT;
    const int tid  = threadIdx.x;

    __shared__ int   sxm[B], sym[B], szm[B];
    __shared__ float sxs[B], sys[B], szs[B];
    __shared__ float sred[NWARP * 128];
    __shared__ unsigned int slast;

    const float px = pos[atom*3+0];
    const float py = pos[atom*3+1];
    const float pz = pos[atom*3+2];

    if (tid < B) {
        const float cmx = rintf(px / AH);
        const float cmy = rintf(py / AH);
        const float cmz = rintf(pz / AH);
        const int cx = (int)cmx, cy = (int)cmy, cz = (int)cmz;
        const int off = tid - RMAX;
        sxm[tid] = ((cx + off) % G + G) % G;
        sym[tid] = ((cy + off) % G + G) % G;
        szm[tid] = ((cz + off) % G + G) % G;
        const float offf = (float)off;
        sxs[tid] = offf * AH - (px - AH * cmx);
        sys[tid] = offf * AH - (py - AH * cmy);
        szs[tid] = offf * AH - (pz - AH * cmz);
    }
    __syncthreads();

    // 64 packed accumulators: c2[m*8+p] = (coef[m][2p], coef[m][2p+1])
    unsigned long long c2[64];
    #pragma unroll
    for (int v = 0; v < 64; v++) c2[v] = 0ull;

    for (int idx = part * THREADS + tid; idx < NCELL; idx += SPLIT * THREADS) {
        const int i   = idx / (B * B);
        const int rem = idx - i * (B * B);
        const int j   = rem / B;
        const int k   = rem - j * B;

        const float x = sxs[i], y = sys[j], z = szs[k];
        const float r2 = x*x + y*y + z*z;
        if (r2 >= ROF * ROF || r2 < 1e-24f) continue;

        const float srho = __ldg(&rho[(sxm[i] * G + sym[j]) * G + szm[k]]);

        const float inv = rsqrtf(r2);
        const float r   = r2 * inv;
        const float u   = ROF - r;
        const float xh = x * inv, yh = y * inv, zh = z * inv;
        const float xh2 = xh*xh, yh2 = yh*yh, zh2 = zh*zh;

        // real spherical harmonics (Cartesian form), packed in adjacent pairs
        unsigned long long yp[8];
        {
            const float Y0  = 0.28209479177387814f;
            const float Y1  = 0.4886025119029199f * yh;
            const float Y2  = 0.4886025119029199f * zh;
            const float Y3  = 0.4886025119029199f * xh;
            const float Y4  = 1.0925484305920792f * xh * yh;
            const float Y5  = 1.0925484305920792f * yh * zh;
            const float Y6  = 0.31539156525252005f * (3.0f * zh2 - 1.0f);
            const float Y7  = 1.0925484305920792f * xh * zh;
            const float Y8  = 0.5462742152960396f * (xh2 - yh2);
            const float Y9  = 0.5900435899266435f * yh * (3.0f * xh2 - yh2);
            const float Y10 = 2.890611442640554f  * xh * yh * zh;
            const float Y11 = 0.4570457994644658f * yh * (5.0f * zh2 - 1.0f);
            const float Y12 = 0.3731763325901154f * zh * (5.0f * zh2 - 3.0f);
            const float Y13 = 0.4570457994644658f * xh * (5.0f * zh2 - 1.0f);
            const float Y14 = 1.445305721320277f  * zh * (xh2 - yh2);
            const float Y15 = 0.5900435899266435f * xh * (xh2 - 3.0f * yh2);
            yp[0] = pk2(Y0,  Y1);  yp[1] = pk2(Y2,  Y3);
            yp[2] = pk2(Y4,  Y5);  yp[3] = pk2(Y6,  Y7);
            yp[4] = pk2(Y8,  Y9);  yp[5] = pk2(Y10, Y11);
            yp[6] = pk2(Y12, Y13); yp[7] = pk2(Y14, Y15);
        }

        // radial basis * density, packed power chain: t[m] = rho*r^2*u^(m+2)
        const float p0 = r2 * u * u * srho;
        unsigned long long tp = pk2(p0, p0);
        const unsigned long long up = pk2(u, u);

        #pragma unroll
        for (int m = 0; m < 8; m++) {
            #pragma unroll
            for (int q = 0; q < 8; q++)
                fma2(c2[m*8 + q], tp, yp[q]);
            if (m < 7) tp = mul2(tp, up);
        }
    }

    // warp shuffle reduction -> smem -> per-value block sum
    const int lane = tid & 31, warp = tid >> 5;
    #pragma unroll
    for (int v = 0; v < 64; v++) {
        float lo, hi;
        upk2(lo, hi, c2[v]);
        lo += __shfl_down_sync(0xffffffffu, lo, 16);
        hi += __shfl_down_sync(0xffffffffu, hi, 16);
        lo += __shfl_down_sync(0xffffffffu, lo, 8);
        hi += __shfl_down_sync(0xffffffffu, hi, 8);
        lo += __shfl_down_sync(0xffffffffu, lo, 4);
        hi += __shfl_down_sync(0xffffffffu, hi, 4);
        lo += __shfl_down_sync(0xffffffffu, lo, 2);
        hi += __shfl_down_sync(0xffffffffu, hi, 2);
        lo += __shfl_down_sync(0xffffffffu, lo, 1);
        hi += __shfl_down_sync(0xffffffffu, hi, 1);
        if (lane == 0) {
            sred[warp * 128 + 2*v]     = lo;
            sred[warp * 128 + 2*v + 1] = hi;
        }
    }
    __syncthreads();

    if (tid < 128) {
        float s = 0.0f;
        #pragma unroll
        for (int w = 0; w < NWARP; w++) s += sred[w * 128 + tid];
        g_partial[blk * 128 + tid] = s;
    }
    __threadfence();
    __syncthreads();

    if (tid == 0) {
        const unsigned int ticket = atomicAdd(&g_count[atom], 1u);
        slast = (ticket == SPLIT - 1) ? 1u : 0u;
    }
    __syncthreads();

    if (slast) {
        // this is the last block for this atom: combine partials (fixed order),
        // apply whitening W and VCELL, write output, reset counter.
        const volatile float* gp = g_partial;
        if (tid < 128) {
            float s = 0.0f;
            #pragma unroll
            for (int p = 0; p < SPLIT; p++)
                s += gp[(atom * SPLIT + p) * 128 + tid];
            sred[tid] = s;
        }
        __syncthreads();
        if (tid < 128) {
            const int n = tid >> 4;   // radial index
            const int q = tid & 15;   // angular index
            float o = 0.0f;
            #pragma unroll
            for (int m = 0; m < 8; m++)
                o = fmaf(W[n * 8 + m], sred[m * 16 + q], o);
            out[atom * 128 + tid] = o * VCELLF;
        }
        if (tid == 0) g_count[atom] = 0u;
    }
}

extern "C" void kernel_launch(void* const* d_in, const int* in_sizes, int n_in,
                              void* d_out, int out_size)
{
    const float* rho = (const float*)d_in[0];   // 180^3
    const float* pos = (const float*)d_in[1];   // 64 x 3
    const float* W   = (const float*)d_in[2];   // 8 x 8
    float* out = (float*)d_out;                 // 64 x 128

    proj_kernel<<<NA * SPLIT, THREADS>>>(rho, pos, W, out);
}

// round 3
// speedup vs baseline: 1.3067x; 1.3067x over previous
#include <cuda_runtime.h>

#define G       180
#define NA      64
#define Bx      27
#define RMAX    13
#define NCELL   (Bx*Bx*Bx)   // 19683
#define SPLIT   2
#define THREADS 256
#define NWARP   (THREADS/32)
#define AH      0.2f
#define ROF     2.5f
#define RO2F    6.25f
#define VCELLF  0.008f
#define STRIDE  (SPLIT*THREADS)      // 512
#define CSTEP   (4*STRIDE)           // 2048 cells per iteration
#define NITER   ((NCELL + CSTEP - 1) / CSTEP)   // 10

__device__ float        g_partial[NA * SPLIT * 128];
__device__ unsigned int g_count[NA];

__device__ __forceinline__ unsigned long long pk2(float lo, float hi) {
    unsigned long long r;
    asm("mov.b64 %0, {%1, %2};" : "=l"(r) : "f"(lo), "f"(hi));
    return r;
}
__device__ __forceinline__ void upk2(float& lo, float& hi, unsigned long long v) {
    asm("mov.b64 {%0, %1}, %2;" : "=f"(lo), "=f"(hi) : "l"(v));
}
__device__ __forceinline__ void fma2(unsigned long long& d,
                                     unsigned long long a, unsigned long long b) {
    asm("fma.rn.f32x2 %0, %1, %2, %0;" : "+l"(d) : "l"(a), "l"(b));
}
__device__ __forceinline__ unsigned long long mul2(unsigned long long a,
                                                   unsigned long long b) {
    unsigned long long r;
    asm("mul.rn.f32x2 %0, %1, %2;" : "=l"(r) : "l"(a), "l"(b));
    return r;
}

__global__ __launch_bounds__(THREADS, 1)
void proj_kernel(const float* __restrict__ rho, const float* __restrict__ pos,
                 const float* __restrict__ W, float* __restrict__ out)
{
    const int blk  = blockIdx.x;
    const int atom = blk >> 1;          // SPLIT = 2
    const int part = blk & 1;
    const int tid  = threadIdx.x;

    // tab[ij] = { rowbase (as int), x^2+y^2, x, y } ; ztab[k] = { z, zindex }
    __shared__ float4 tab[Bx * Bx];
    __shared__ float2 ztab[Bx];
    __shared__ float  sred[NWARP * 128];
    __shared__ unsigned int slast;

    const float px = pos[atom*3+0];
    const float py = pos[atom*3+1];
    const float pz = pos[atom*3+2];
    const float cmx = rintf(px / AH);
    const float cmy = rintf(py / AH);
    const float cmz = rintf(pz / AH);
    const int cx = (int)cmx, cy = (int)cmy, cz = (int)cmz;
    const float dx = px - AH * cmx;
    const float dy = py - AH * cmy;
    const float dz = pz - AH * cmz;

    for (int ij = tid; ij < Bx * Bx; ij += THREADS) {
        const int i = ij / Bx;
        const int j = ij - i * Bx;
        int vx = cx + (i - RMAX);  vx = (vx < 0) ? vx + G : (vx >= G ? vx - G : vx);
        int vy = cy + (j - RMAX);  vy = (vy < 0) ? vy + G : (vy >= G ? vy - G : vy);
        const float xs = (float)(i - RMAX) * AH - dx;
        const float ys = (float)(j - RMAX) * AH - dy;
        tab[ij] = make_float4(__int_as_float((vx * G + vy) * G),
                              xs * xs + ys * ys, xs, ys);
    }
    if (tid < Bx) {
        int vz = cz + (tid - RMAX);  vz = (vz < 0) ? vz + G : (vz >= G ? vz - G : vz);
        const float zs = (float)(tid - RMAX) * AH - dz;
        ztab[tid] = make_float2(zs, __int_as_float(vz));
    }
    __syncthreads();

    // packed accumulators: c2[m*8+p] = (coef[m][2p], coef[m][2p+1])
    unsigned long long c2[64];
    #pragma unroll
    for (int v = 0; v < 64; v++) c2[v] = 0ull;

    const int tbase = part * THREADS + tid;

    for (int it = 0; it < NITER; it++) {
        const int ibase = it * CSTEP + tbase;

        // ---- front-batched loads for 4 cells ----
        float4 t4[4];  float2 z2[4];  float srho[4];  bool vld[4];
        #pragma unroll
        for (int s = 0; s < 4; s++) {
            int id = ibase + s * STRIDE;
            const bool v = (id < NCELL);
            id = v ? id : 0;
            const int ij = id / Bx;
            const int k  = id - ij * Bx;
            const float4 t = tab[ij];
            const float2 zz = ztab[k];
            srho[s] = __ldg(rho + __float_as_int(t.x) + __float_as_int(zz.y));
            t4[s] = t;  z2[s] = zz;  vld[s] = v;
        }

        // ---- process the 4 cells ----
        #pragma unroll
        for (int s = 0; s < 4; s++) {
            const float x = t4[s].z, y = t4[s].w, z = z2[s].x;
            const float r2 = fmaf(z, z, t4[s].y);
            const bool valid = vld[s] && (r2 < RO2F);
            if (__ballot_sync(0xffffffffu, valid) == 0u) continue;  // warp-uniform

            const float inv = rsqrtf(fmaxf(r2, 1e-24f));
            const float r   = r2 * inv;
            const float u   = ROF - r;
            const float p0  = valid ? r2 * u * u * srho[s] : 0.0f;
            const float xh = x * inv, yh = y * inv, zh = z * inv;
            const float xh2 = xh*xh, yh2 = yh*yh, zh2 = zh*zh;

            unsigned long long yp[8];
            {
                const float Y0  = 0.28209479177387814f;
                const float Y1  = 0.4886025119029199f * yh;
                const float Y2  = 0.4886025119029199f * zh;
                const float Y3  = 0.4886025119029199f * xh;
                const float Y4  = 1.0925484305920792f * xh * yh;
                const float Y5  = 1.0925484305920792f * yh * zh;
                const float Y6  = 0.31539156525252005f * (3.0f * zh2 - 1.0f);
                const float Y7  = 1.0925484305920792f * xh * zh;
                const float Y8  = 0.5462742152960396f * (xh2 - yh2);
                const float Y9  = 0.5900435899266435f * yh * (3.0f * xh2 - yh2);
                const float Y10 = 2.890611442640554f  * xh * yh * zh;
                const float Y11 = 0.4570457994644658f * yh * (5.0f * zh2 - 1.0f);
                const float Y12 = 0.3731763325901154f * zh * (5.0f * zh2 - 3.0f);
                const float Y13 = 0.4570457994644658f * xh * (5.0f * zh2 - 1.0f);
                const float Y14 = 1.445305721320277f  * zh * (xh2 - yh2);
                const float Y15 = 0.5900435899266435f * xh * (xh2 - 3.0f * yh2);
                yp[0] = pk2(Y0,  Y1);  yp[1] = pk2(Y2,  Y3);
                yp[2] = pk2(Y4,  Y5);  yp[3] = pk2(Y6,  Y7);
                yp[4] = pk2(Y8,  Y9);  yp[5] = pk2(Y10, Y11);
                yp[6] = pk2(Y12, Y13); yp[7] = pk2(Y14, Y15);
            }

            unsigned long long tp = pk2(p0, p0);
            const unsigned long long up = pk2(u, u);
            #pragma unroll
            for (int m = 0; m < 8; m++) {
                #pragma unroll
                for (int q = 0; q < 8; q++)
                    fma2(c2[m*8 + q], tp, yp[q]);
                if (m < 7) tp = mul2(tp, up);
            }
        }
    }

    // ---- warp shuffle reduction -> smem -> block sum ----
    const int lane = tid & 31, warp = tid >> 5;
    #pragma unroll
    for (int v = 0; v < 64; v++) {
        float lo, hi;
        upk2(lo, hi, c2[v]);
        lo += __shfl_down_sync(0xffffffffu, lo, 16);
        hi += __shfl_down_sync(0xffffffffu, hi, 16);
        lo += __shfl_down_sync(0xffffffffu, lo, 8);
        hi += __shfl_down_sync(0xffffffffu, hi, 8);
        lo += __shfl_down_sync(0xffffffffu, lo, 4);
        hi += __shfl_down_sync(0xffffffffu, hi, 4);
        lo += __shfl_down_sync(0xffffffffu, lo, 2);
        hi += __shfl_down_sync(0xffffffffu, hi, 2);
        lo += __shfl_down_sync(0xffffffffu, lo, 1);
        hi += __shfl_down_sync(0xffffffffu, hi, 1);
        if (lane == 0) {
            sred[warp * 128 + 2*v]     = lo;
            sred[warp * 128 + 2*v + 1] = hi;
        }
    }
    __syncthreads();

    if (tid < 128) {
        float s = 0.0f;
        #pragma unroll
        for (int w = 0; w < NWARP; w++) s += sred[w * 128 + tid];
        g_partial[blk * 128 + tid] = s;
    }
    __threadfence();
    __syncthreads();

    if (tid == 0) {
        const unsigned int ticket = atomicAdd(&g_count[atom], 1u);
        slast = (ticket == SPLIT - 1) ? 1u : 0u;
    }
    __syncthreads();

    if (slast) {
        const volatile float* gp = g_partial;
        if (tid < 128) {
            float s = 0.0f;
            #pragma unroll
            for (int p = 0; p < SPLIT; p++)
                s += gp[(atom * SPLIT + p) * 128 + tid];
            sred[tid] = s;
        }
        __syncthreads();
        if (tid < 128) {
            const int n = tid >> 4;
            const int q = tid & 15;
            float o = 0.0f;
            #pragma unroll
            for (int m = 0; m < 8; m++)
                o = fmaf(W[n * 8 + m], sred[m * 16 + q], o);
            out[atom * 128 + tid] = o * VCELLF;
        }
        if (tid == 0) g_count[atom] = 0u;
    }
}

extern "C" void kernel_launch(void* const* d_in, const int* in_sizes, int n_in,
                              void* d_out, int out_size)
{
    const float* rho = (const float*)d_in[0];   // 180^3
    const float* pos = (const float*)d_in[1];   // 64 x 3
    const float* W   = (const float*)d_in[2];   // 8 x 8
    float* out = (float*)d_out;                 // 64 x 128

    proj_kernel<<<NA * SPLIT, THREADS>>>(rho, pos, W, out);
}